// round 8
// baseline (speedup 1.0000x reference)
#include <cuda_runtime.h>
#include <math.h>
#include <stdint.h>

// Problem constants
#define TT   256
#define BB   32
#define DD   512
#define HH   8
#define HDd  64
#define ETA  4
#define RR   4
#define FEAT 256
#define MM   (TT*BB)        // 8192
#define LDP  2816           // padded proj row: 5*512 + 96 p + pad  (11*256)
#define WROWS 2560          // 5*H*HD

// Scratch (device globals; allocation-free per harness rules)
__device__ float g_x   [(size_t)MM * DD];
__device__ float g_w5  [(size_t)LDP * DD];     // tf32 Wq|Wk|Wv|Wb|Wg|Wp1|Wp2|Wp3|0pad
__device__ float g_wo  [(size_t)DD * DD];
__device__ float g_proj[(size_t)MM * LDP];
__device__ float g_attn[(size_t)MM * DD];

__device__ __forceinline__ float tf32r(float x) {
    float r;
    asm("cvt.rna.tf32.f32 %0, %1;" : "=f"(r) : "f"(x));
    return r;
}

__global__ void cvt1_kernel(float* __restrict__ dst, const float* __restrict__ src, int n) {
    int i = blockIdx.x * 256 + threadIdx.x;
    if (i < n) dst[i] = tf32r(src[i]);
}
__global__ void cvt5_kernel(float* __restrict__ dst,
                            const float* __restrict__ s0, const float* __restrict__ s1,
                            const float* __restrict__ s2, const float* __restrict__ s3,
                            const float* __restrict__ s4, int per) {
    int i = blockIdx.x * 256 + threadIdx.x;
    if (i >= 5 * per) return;
    int seg = i / per, j = i - seg * per;
    const float* s = (seg == 0) ? s0 : (seg == 1) ? s1 : (seg == 2) ? s2 : (seg == 3) ? s3 : s4;
    dst[i] = tf32r(s[j]);
}
// p1|p2|p3 (32 rows each) + zero pad up to 256 rows total (rows 2560..2815 of w5)
__global__ void cvtp_kernel(float* __restrict__ dst,
                            const float* __restrict__ s0, const float* __restrict__ s1,
                            const float* __restrict__ s2, int per /*=16384*/) {
    int i = blockIdx.x * 256 + threadIdx.x;
    if (i >= 8 * per) return;
    int seg = i / per, j = i - seg * per;
    float v = 0.f;
    if (seg == 0) v = tf32r(s0[j]);
    else if (seg == 1) v = tf32r(s1[j]);
    else if (seg == 2) v = tf32r(s2[j]);
    dst[i] = v;
}

// ---------------------------------------------------------------------------
// TF32 tensor-core GEMM: C[M x N] = A[M x K] @ B[N x K]^T (+bias)
// Block tile 128 x 256, warp tile 64 x 64 (8 warps, 2m x 4n), BK=16,
// 3-stage cp.async ring (dynamic smem, 92KB), one __syncthreads per K-iter.
// ---------------------------------------------------------------------------
#define GBM 128
#define GBN 256
#define GBK 16
#define KPAD 20
#define STG 3
#define SMEM_GEMM (STG * (GBM + GBN) * KPAD * 4)   // 92160 bytes

__global__ __launch_bounds__(256) void mma_gemm(
    const float* __restrict__ A, const float* __restrict__ B,
    float* __restrict__ C, int M, int N, int K, int ldc, const float* __restrict__ bias)
{
    extern __shared__ float dynsm[];
    float* As = dynsm;                          // [STG][GBM*KPAD]
    float* Bs = dynsm + STG * GBM * KPAD;       // [STG][GBN*KPAD]

    const int tid  = threadIdx.x;
    const int lane = tid & 31;
    const int wid  = tid >> 5;
    const int wm   = wid & 1;    // 2 m-warps -> 64 rows each
    const int wn   = wid >> 1;   // 4 n-warps -> 64 cols each
    const int m0   = blockIdx.y * GBM;
    const int n0   = blockIdx.x * GBN;

    const unsigned asbase = (unsigned)__cvta_generic_to_shared(As);
    const unsigned bsbase = (unsigned)__cvta_generic_to_shared(Bs);

    const int a_r  = lane & 15;
    const int a_k4 = (lane >> 4) * 4;
    const int b_n  = lane & 7;
    const int b_k4 = (lane >> 3) * 4;

    float acc[4][8][4];
#pragma unroll
    for (int i = 0; i < 4; i++)
#pragma unroll
        for (int j = 0; j < 8; j++)
#pragma unroll
            for (int c = 0; c < 4; c++) acc[i][j][c] = 0.f;

    auto prefetch = [&](int it, int buf) {
        const int k0 = it * GBK;
        // A tile: 128 x 16 = 512 float4
#pragma unroll
        for (int i = 0; i < 2; i++) {
            int idx = tid + i * 256;
            int r   = idx >> 2;
            int k4  = (idx & 3) * 4;
            unsigned da = asbase + (unsigned)((buf * GBM * KPAD + r * KPAD + k4) * 4);
            const float* sa = A + (size_t)(m0 + r) * K + k0 + k4;
            asm volatile("cp.async.cg.shared.global [%0], [%1], 16;\n" :: "r"(da), "l"(sa));
        }
        // B tile: 256 x 16 = 1024 float4
#pragma unroll
        for (int i = 0; i < 4; i++) {
            int idx = tid + i * 256;
            int r   = idx >> 2;
            int k4  = (idx & 3) * 4;
            unsigned db = bsbase + (unsigned)((buf * GBN * KPAD + r * KPAD + k4) * 4);
            const float* sb = B + (size_t)(n0 + r) * K + k0 + k4;
            asm volatile("cp.async.cg.shared.global [%0], [%1], 16;\n" :: "r"(db), "l"(sb));
        }
        asm volatile("cp.async.commit_group;\n");
    };

    const int NIT = K / GBK;
    prefetch(0, 0);
    if (NIT > 1) prefetch(1, 1);

    int buf = 0, pf = 2;
    for (int it = 0; it < NIT; ++it) {
        if (it + 1 < NIT) {
            asm volatile("cp.async.wait_group 1;\n");
        } else {
            asm volatile("cp.async.wait_group 0;\n");
        }
        __syncthreads();

        // B fragments: 8 n8-tiles per warp, x4 ldmatrix covers k0..15
        uint32_t bf[8][4];
#pragma unroll
        for (int nt = 0; nt < 8; nt++) {
            unsigned addr = bsbase + (unsigned)((buf * GBN * KPAD +
                            (wn * 64 + nt * 8 + b_n) * KPAD + b_k4) * 4);
            asm volatile("ldmatrix.sync.aligned.m8n8.x4.shared.b16 {%0,%1,%2,%3}, [%4];"
                : "=r"(bf[nt][0]), "=r"(bf[nt][1]), "=r"(bf[nt][2]), "=r"(bf[nt][3])
                : "r"(addr));
        }

#pragma unroll
        for (int k8 = 0; k8 < 2; k8++) {
            uint32_t af[4][4];
#pragma unroll
            for (int mt = 0; mt < 4; mt++) {
                unsigned addr = asbase + (unsigned)((buf * GBM * KPAD +
                                (wm * 64 + mt * 16 + a_r) * KPAD + k8 * 8 + a_k4) * 4);
                asm volatile("ldmatrix.sync.aligned.m8n8.x4.shared.b16 {%0,%1,%2,%3}, [%4];"
                    : "=r"(af[mt][0]), "=r"(af[mt][1]), "=r"(af[mt][2]), "=r"(af[mt][3])
                    : "r"(addr));
            }
#pragma unroll
            for (int mt = 0; mt < 4; mt++)
#pragma unroll
                for (int nt = 0; nt < 8; nt++) {
                    asm volatile(
                        "mma.sync.aligned.m16n8k8.row.col.f32.tf32.tf32.f32 "
                        "{%0,%1,%2,%3}, {%4,%5,%6,%7}, {%8,%9}, {%0,%1,%2,%3};"
                        : "+f"(acc[mt][nt][0]), "+f"(acc[mt][nt][1]),
                          "+f"(acc[mt][nt][2]), "+f"(acc[mt][nt][3])
                        : "r"(af[mt][0]), "r"(af[mt][1]), "r"(af[mt][2]), "r"(af[mt][3]),
                          "r"(bf[nt][k8 * 2]), "r"(bf[nt][k8 * 2 + 1]));
                }
        }

        if (it + 2 < NIT) prefetch(it + 2, pf);
        buf = (buf + 1 == STG) ? 0 : buf + 1;
        pf  = (pf  + 1 == STG) ? 0 : pf + 1;
    }

#pragma unroll
    for (int mt = 0; mt < 4; mt++) {
        int row = m0 + wm * 64 + mt * 16 + (lane >> 2);
#pragma unroll
        for (int nt = 0; nt < 8; nt++) {
            int col = n0 + wn * 64 + nt * 8 + (lane & 3) * 2;
            float b0v = bias ? bias[col]     : 0.f;
            float b1v = bias ? bias[col + 1] : 0.f;
            float2 v0 = make_float2(acc[mt][nt][0] + b0v, acc[mt][nt][1] + b1v);
            float2 v1 = make_float2(acc[mt][nt][2] + b0v, acc[mt][nt][3] + b1v);
            *reinterpret_cast<float2*>(&C[(size_t)row * ldc + col]) = v0;
            *reinterpret_cast<float2*>(&C[(size_t)(row + 8) * ldc + col]) = v1;
        }
    }
}

// ---------------------------------------------------------------------------
// Recurrence kernel (unchanged from round 6 winner, LDP stride)
// ---------------------------------------------------------------------------
__device__ __forceinline__ float sigf(float x) {
    return 1.f / (1.f + __expf(-x));
}

#define NBUF 4

__global__ __launch_bounds__(64) void recur_kernel(
    const float* __restrict__ proj,   // [MM][LDP] q|k|v|b|g|p1|p2|p3
    const int*   __restrict__ term,
    const float* __restrict__ tkp,
    const float* __restrict__ tvp,
    const float* __restrict__ sprev,
    const float* __restrict__ tick,
    float* __restrict__ attn)
{
    const int bh = blockIdx.x;
    const int b = bh >> 3;
    const int h = bh & 7;
    const int d = threadIdx.x;

    __shared__ __align__(16) float sstage[NBUF][5][64];
    __shared__ __align__(16) float sp[NBUF][3][4];
    __shared__ int sterm[NBUF];
    __shared__ float red[2][5][2];

    float ks[4][4], ss[4], vs[4];
#pragma unroll
    for (int e = 0; e < 4; e++) {
#pragma unroll
        for (int r = 0; r < 4; r++)
            ks[e][r] = tkp[((size_t)(b * RR + r) * HH + h) * FEAT + e * 64 + d];
        ss[e] = sprev[((size_t)(b * HH + h)) * FEAT + e * 64 + d];
    }
#pragma unroll
    for (int r = 0; r < 4; r++)
        vs[r] = tvp[((size_t)(b * RR + r) * HH + h) * HDd + d];

    const float PI = 3.14159265358979323846f;
    const float tk = tick[b];

    float cr0, cr1, cr2, cr3, sr0, sr1, sr2, sr3;
    float cw0, cw1, cw2, cw3, sw0, sw1, sw2, sw3;
    {
        float om0 = -PI;
        float om1 = -PI + 2.f * PI / 3.f;
        float om2 = -PI + 4.f * PI / 3.f;
        float om3 = PI;
        float a;
        a = (1.f + tk) * om0; cr0 = cosf(a); sr0 = sinf(a);
        a = (1.f + tk) * om1; cr1 = cosf(a); sr1 = sinf(a);
        a = (1.f + tk) * om2; cr2 = cosf(a); sr2 = sinf(a);
        a = (1.f + tk) * om3; cr3 = cosf(a); sr3 = sinf(a);
        cw0 = cosf(om0); sw0 = sinf(om0);
        cw1 = cosf(om1); sw1 = sinf(om1);
        cw2 = cosf(om2); sw2 = sinf(om2);
        cw3 = cosf(om3); sw3 = sinf(om3);
    }

    auto stage = [&](int t, int buf) {
        const int m = t * BB + b;
        {
            const int seg = d >> 4;
            const int j = (d & 15) * 4;
            const float* src = proj + (size_t)m * LDP + seg * 512 + h * HDd + j;
            unsigned dst = (unsigned)__cvta_generic_to_shared(&sstage[buf][seg][j]);
            asm volatile("cp.async.ca.shared.global [%0], [%1], 16;\n" :: "r"(dst), "l"(src));
        }
        if (d < 16) {
            const float* src = proj + (size_t)m * LDP + 4 * 512 + h * HDd + d * 4;
            unsigned dst = (unsigned)__cvta_generic_to_shared(&sstage[buf][4][d * 4]);
            asm volatile("cp.async.ca.shared.global [%0], [%1], 16;\n" :: "r"(dst), "l"(src));
        } else if (d < 19) {
            const int j = d - 16;
            const float* src = proj + (size_t)m * LDP + WROWS + j * 32 + h * ETA;
            unsigned dst = (unsigned)__cvta_generic_to_shared(&sp[buf][j][0]);
            asm volatile("cp.async.ca.shared.global [%0], [%1], 16;\n" :: "r"(dst), "l"(src));
        } else if (d == 19) {
            const int* src = term + m;
            unsigned dst = (unsigned)__cvta_generic_to_shared(&sterm[buf]);
            asm volatile("cp.async.ca.shared.global [%0], [%1], 4;\n" :: "r"(dst), "l"(src));
        }
        asm volatile("cp.async.commit_group;\n");
    };

    stage(0, 0);
    stage(1, 1);
    stage(2, 2);
    asm volatile("cp.async.wait_group 2;\n");
    __syncthreads();

    const int warp = d >> 5;

    for (int t = 0; t < TT; t++) {
        const int buf = t & (NBUF - 1);

        const float qd   = sstage[buf][0][d];
        const float kd   = sstage[buf][1][d];
        const float vv   = sstage[buf][2][d];
        const float bd   = sigf(sstage[buf][3][d]);
        const float gd   = sigf(sstage[buf][4][d]);
        const float tf   = 1.f - (float)sterm[buf];

        float v0 = 0.f, v1 = 0.f, v2 = 0.f, v3 = 0.f, v4 = 0.f;
#pragma unroll
        for (int e = 0; e < 4; e++) {
            const float phi = fmaxf(qd * sp[buf][1][e], 0.f);
            const float psi = fmaxf(kd * sp[buf][0][e], 0.f);
            const float gf  = gd * sigf(sp[buf][2][e]);
            const float gk  = psi * gf;
            const float dg  = (1.f - gf) * tf;

            ss[e] = dg * ss[e] + gk;
            v4 += ss[e] * phi;

            ks[e][0] = dg * ks[e][0] + gk * cr0;  v0 += ks[e][0] * phi;
            ks[e][1] = dg * ks[e][1] + gk * cr1;  v1 += ks[e][1] * phi;
            ks[e][2] = dg * ks[e][2] + gk * cr2;  v2 += ks[e][2] * phi;
            ks[e][3] = dg * ks[e][3] + gk * cr3;  v3 += ks[e][3] * phi;
        }

        const float bv = vv * bd;
        const float om = (1.f - bd) * tf;
        vs[0] = om * vs[0] + bv * cr0;
        vs[1] = om * vs[1] + bv * cr1;
        vs[2] = om * vs[2] + bv * cr2;
        vs[3] = om * vs[3] + bv * cr3;

#pragma unroll
        for (int o = 16; o > 0; o >>= 1) {
            v0 += __shfl_xor_sync(0xffffffffu, v0, o);
            v1 += __shfl_xor_sync(0xffffffffu, v1, o);
            v2 += __shfl_xor_sync(0xffffffffu, v2, o);
            v3 += __shfl_xor_sync(0xffffffffu, v3, o);
            v4 += __shfl_xor_sync(0xffffffffu, v4, o);
        }
        const int pb = t & 1;
        if ((d & 31) == 0) {
            red[pb][0][warp] = v0;
            red[pb][1][warp] = v1;
            red[pb][2][warp] = v2;
            red[pb][3][warp] = v3;
            red[pb][4][warp] = v4;
        }

        if (t + 3 < TT) {
            stage(t + 3, (t + 3) & (NBUF - 1));
            asm volatile("cp.async.wait_group 2;\n");
        } else if (t + 2 < TT) {
            asm volatile("cp.async.wait_group 1;\n");
        } else {
            asm volatile("cp.async.wait_group 0;\n");
        }
        __syncthreads();

        const float kdq0 = red[pb][0][0] + red[pb][0][1];
        const float kdq1 = red[pb][1][0] + red[pb][1][1];
        const float kdq2 = red[pb][2][0] + red[pb][2][1];
        const float kdq3 = red[pb][3][0] + red[pb][3][1];
        const float norm = red[pb][4][0] + red[pb][4][1];

        const float kv = vs[0] * kdq0 + vs[1] * kdq1 + vs[2] * kdq2 + vs[3] * kdq3;
        const int m = t * BB + b;
        attn[(size_t)m * DD + h * HDd + d] = tf32r(kv / (8.f * norm + 1e-6f));

        float c2, s2;
        c2 = cr0 * cw0 - sr0 * sw0; s2 = sr0 * cw0 + cr0 * sw0; cr0 = c2; sr0 = s2;
        c2 = cr1 * cw1 - sr1 * sw1; s2 = sr1 * cw1 + cr1 * sw1; cr1 = c2; sr1 = s2;
        c2 = cr2 * cw2 - sr2 * sw2; s2 = sr2 * cw2 + cr2 * sw2; cr2 = c2; sr2 = s2;
        c2 = cr3 * cw3 - sr3 * sw3; s2 = sr3 * cw3 + cr3 * sw3; cr3 = c2; sr3 = s2;
    }
}

// ---------------------------------------------------------------------------
extern "C" void kernel_launch(void* const* d_in, const int* in_sizes, int n_in,
                              void* d_out, int out_size)
{
    const float* inputs = (const float*)d_in[0];
    const int*   term   = (const int*)d_in[1];
    const float* tkp    = (const float*)d_in[2];
    const float* tvp    = (const float*)d_in[3];
    const float* sprev  = (const float*)d_in[4];
    const float* tick   = (const float*)d_in[5];
    const float* Wq     = (const float*)d_in[6];
    const float* Wk     = (const float*)d_in[7];
    const float* Wv     = (const float*)d_in[8];
    const float* Wb     = (const float*)d_in[9];
    const float* Wg     = (const float*)d_in[10];
    const float* Wp1    = (const float*)d_in[11];
    const float* Wp2    = (const float*)d_in[12];
    const float* Wp3    = (const float*)d_in[13];
    const float* Wo     = (const float*)d_in[14];
    const float* bo     = (const float*)d_in[15];

    void* p;
    cudaGetSymbolAddress(&p, g_x);    float* x    = (float*)p;
    cudaGetSymbolAddress(&p, g_w5);   float* w5   = (float*)p;
    cudaGetSymbolAddress(&p, g_wo);   float* wo   = (float*)p;
    cudaGetSymbolAddress(&p, g_proj); float* proj = (float*)p;
    cudaGetSymbolAddress(&p, g_attn); float* attn = (float*)p;

    const int WSZ = HH * HDd * DD;    // 262144
    const int PSZ = HH * ETA * DD;    // 16384

    cudaFuncSetAttribute(mma_gemm, cudaFuncAttributeMaxDynamicSharedMemorySize, SMEM_GEMM);

    cvt1_kernel<<<(MM * DD + 255) / 256, 256>>>(x, inputs, MM * DD);
    cvt5_kernel<<<(5 * WSZ + 255) / 256, 256>>>(w5, Wq, Wk, Wv, Wb, Wg, WSZ);
    cvtp_kernel<<<(8 * PSZ + 255) / 256, 256>>>(w5 + (size_t)WROWS * DD, Wp1, Wp2, Wp3, PSZ);
    cvt1_kernel<<<(WSZ + 255) / 256, 256>>>(wo, Wo, WSZ);

    // 1) Fused projection: (8192 x 2816) — q,k,v,beta,gamma,p1,p2,p3 (+pad)
    {
        dim3 grid(LDP / GBN, MM / GBM);   // (11, 64)
        mma_gemm<<<grid, 256, SMEM_GEMM>>>(x, w5, proj, MM, LDP, DD, LDP, nullptr);
    }
    // 2) Recurrence (64 threads per (b,h), one barrier per step)
    recur_kernel<<<BB * HH, 64>>>(proj, term, tkp, tvp, sprev, tick, attn);

    // 3) Output projection: out = attn @ Wo^T + bo  (8192 x 512)
    {
        dim3 grid(DD / GBN, MM / GBM);    // (2, 64)
        mma_gemm<<<grid, 256, SMEM_GEMM>>>(attn, wo, (float*)d_out, MM, DD, DD, DD, bo);
    }
}

// round 9
// speedup vs baseline: 1.2871x; 1.2871x over previous
#include <cuda_runtime.h>
#include <cuda_fp16.h>
#include <math.h>
#include <stdint.h>

// Problem constants
#define TT   256
#define BB   32
#define DD   512
#define HH   8
#define HDd  64
#define ETA  4
#define RR   4
#define FEAT 256
#define MM   (TT*BB)        // 8192
#define LDP  2688           // 5*512 + 96 p + 32 pad  (21*128)
#define WROWS 2560          // 5*H*HD

// Scratch (device globals; allocation-free per harness rules)
__device__ __half g_x   [(size_t)MM * DD];
__device__ __half g_w5  [(size_t)LDP * DD];    // Wq|Wk|Wv|Wb|Wg|Wp1|Wp2|Wp3|0pad
__device__ __half g_wo  [(size_t)DD * DD];
__device__ float  g_proj[(size_t)MM * LDP];
__device__ __half g_attn[(size_t)MM * DD];

__global__ void cvt1_kernel(__half* __restrict__ dst, const float* __restrict__ src, int n) {
    int i = blockIdx.x * 256 + threadIdx.x;
    if (i < n) dst[i] = __float2half_rn(src[i]);
}
__global__ void cvt5_kernel(__half* __restrict__ dst,
                            const float* __restrict__ s0, const float* __restrict__ s1,
                            const float* __restrict__ s2, const float* __restrict__ s3,
                            const float* __restrict__ s4, int per) {
    int i = blockIdx.x * 256 + threadIdx.x;
    if (i >= 5 * per) return;
    int seg = i / per, j = i - seg * per;
    const float* s = (seg == 0) ? s0 : (seg == 1) ? s1 : (seg == 2) ? s2 : (seg == 3) ? s3 : s4;
    dst[i] = __float2half_rn(s[j]);
}
// p1|p2|p3 (32 rows each) + zero pad rows 2656..2687
__global__ void cvtp_kernel(__half* __restrict__ dst,   // dst = g_w5 + WROWS*DD
                            const float* __restrict__ s0, const float* __restrict__ s1,
                            const float* __restrict__ s2, int per /*=16384*/) {
    int i = blockIdx.x * 256 + threadIdx.x;
    if (i >= 4 * per) return;
    int seg = i / per, j = i - seg * per;
    float v = 0.f;
    if (seg == 0) v = s0[j];
    else if (seg == 1) v = s1[j];
    else if (seg == 2) v = s2[j];
    dst[i] = __float2half_rn(v);
}

// ---------------------------------------------------------------------------
// FP16 tensor-core GEMM (fp32 accum): C[M x N] = A[M x K] @ B[N x K]^T (+bias)
// Block tile 128 x 128, warp tile 64 x 32 (8 warps, 2m x 4n), BK=16,
// 3-stage cp.async ring, one __syncthreads per K-iter. mma m16n8k16.
// ---------------------------------------------------------------------------
#define GBM 128
#define GBN 128
#define GBK 16
#define KPADH 24   // halfs; 48B rows -> conflict-free ldmatrix phases
#define STG 3

__global__ __launch_bounds__(256) void mma_gemm(
    const __half* __restrict__ A, const __half* __restrict__ B,
    float* __restrict__ C, int M, int N, int K, int ldc, const float* __restrict__ bias)
{
    __shared__ __half As[STG][GBM * KPADH];
    __shared__ __half Bs[STG][GBN * KPADH];

    const int tid  = threadIdx.x;
    const int lane = tid & 31;
    const int wid  = tid >> 5;
    const int wm   = wid & 1;    // 2 m-warps -> 64 rows
    const int wn   = wid >> 1;   // 4 n-warps -> 32 cols
    const int m0   = blockIdx.y * GBM;
    const int n0   = blockIdx.x * GBN;

    const unsigned asbase = (unsigned)__cvta_generic_to_shared(&As[0][0]);
    const unsigned bsbase = (unsigned)__cvta_generic_to_shared(&Bs[0][0]);

    // ldmatrix lane addressing
    const int a_r  = lane & 15;               // row within 16
    const int a_ch = (lane >> 4) * 8;         // half-col offset: 0 or 8
    const int b_r  = lane & 7;                // row within 8
    const int b_ch = ((lane >> 3) & 1) * 8;   // half-col offset (lanes 0-15 used)

    float acc[4][4][4];
#pragma unroll
    for (int i = 0; i < 4; i++)
#pragma unroll
        for (int j = 0; j < 4; j++)
#pragma unroll
            for (int c = 0; c < 4; c++) acc[i][j][c] = 0.f;

    auto prefetch = [&](int it, int buf) {
        const int k0 = it * GBK;
        // A tile: 128 rows x 16 halfs = 256 x 16B chunks, one per thread
        {
            int row = tid >> 1;
            int c   = tid & 1;
            unsigned da = asbase + (unsigned)((buf * GBM * KPADH + row * KPADH + c * 8) * 2);
            const __half* sa = A + (size_t)(m0 + row) * K + k0 + c * 8;
            asm volatile("cp.async.ca.shared.global [%0], [%1], 16;\n" :: "r"(da), "l"(sa));
        }
        // B tile: 128 rows x 16 halfs
        {
            int row = tid >> 1;
            int c   = tid & 1;
            unsigned db = bsbase + (unsigned)((buf * GBN * KPADH + row * KPADH + c * 8) * 2);
            const __half* sb = B + (size_t)(n0 + row) * K + k0 + c * 8;
            asm volatile("cp.async.ca.shared.global [%0], [%1], 16;\n" :: "r"(db), "l"(sb));
        }
        asm volatile("cp.async.commit_group;\n");
    };

    const int NIT = K / GBK;
    prefetch(0, 0);
    if (NIT > 1) prefetch(1, 1);

    int buf = 0, pf = 2;
    for (int it = 0; it < NIT; ++it) {
        if (it + 1 < NIT) {
            asm volatile("cp.async.wait_group 1;\n");
        } else {
            asm volatile("cp.async.wait_group 0;\n");
        }
        __syncthreads();

        // B fragments: 4 n8-tiles per warp; x2 ldmatrix covers k0..15
        uint32_t bf[4][2];
#pragma unroll
        for (int nt = 0; nt < 4; nt++) {
            unsigned addr = bsbase + (unsigned)((buf * GBN * KPADH +
                            (wn * 32 + nt * 8 + b_r) * KPADH + b_ch) * 2);
            asm volatile("ldmatrix.sync.aligned.m8n8.x2.shared.b16 {%0,%1}, [%2];"
                : "=r"(bf[nt][0]), "=r"(bf[nt][1]) : "r"(addr));
        }
        // A fragments: 4 m16-tiles per warp; x4 covers 16 rows x 16 halfs
        uint32_t af[4][4];
#pragma unroll
        for (int mt = 0; mt < 4; mt++) {
            unsigned addr = asbase + (unsigned)((buf * GBM * KPADH +
                            (wm * 64 + mt * 16 + a_r) * KPADH + a_ch) * 2);
            asm volatile("ldmatrix.sync.aligned.m8n8.x4.shared.b16 {%0,%1,%2,%3}, [%4];"
                : "=r"(af[mt][0]), "=r"(af[mt][1]), "=r"(af[mt][2]), "=r"(af[mt][3])
                : "r"(addr));
        }
#pragma unroll
        for (int mt = 0; mt < 4; mt++)
#pragma unroll
            for (int nt = 0; nt < 4; nt++) {
                asm volatile(
                    "mma.sync.aligned.m16n8k16.row.col.f32.f16.f16.f32 "
                    "{%0,%1,%2,%3}, {%4,%5,%6,%7}, {%8,%9}, {%0,%1,%2,%3};"
                    : "+f"(acc[mt][nt][0]), "+f"(acc[mt][nt][1]),
                      "+f"(acc[mt][nt][2]), "+f"(acc[mt][nt][3])
                    : "r"(af[mt][0]), "r"(af[mt][1]), "r"(af[mt][2]), "r"(af[mt][3]),
                      "r"(bf[nt][0]), "r"(bf[nt][1]));
            }

        if (it + 2 < NIT) prefetch(it + 2, pf);
        buf = (buf + 1 == STG) ? 0 : buf + 1;
        pf  = (pf  + 1 == STG) ? 0 : pf + 1;
    }

#pragma unroll
    for (int mt = 0; mt < 4; mt++) {
        int row = m0 + wm * 64 + mt * 16 + (lane >> 2);
#pragma unroll
        for (int nt = 0; nt < 4; nt++) {
            int col = n0 + wn * 32 + nt * 8 + (lane & 3) * 2;
            float b0v = bias ? bias[col]     : 0.f;
            float b1v = bias ? bias[col + 1] : 0.f;
            float2 v0 = make_float2(acc[mt][nt][0] + b0v, acc[mt][nt][1] + b1v);
            float2 v1 = make_float2(acc[mt][nt][2] + b0v, acc[mt][nt][3] + b1v);
            *reinterpret_cast<float2*>(&C[(size_t)row * ldc + col]) = v0;
            *reinterpret_cast<float2*>(&C[(size_t)(row + 8) * ldc + col]) = v1;
        }
    }
}

// Variant writing __half output (for the out GEMM input path we need attn in half;
// here used for nothing else). Output projection writes float to d_out, so the
// fp32-C kernel above covers both GEMMs; attn half conversion happens in recur.

// ---------------------------------------------------------------------------
// Recurrence kernel (round-6 winner; attn written as half)
// ---------------------------------------------------------------------------
__device__ __forceinline__ float sigf(float x) {
    return 1.f / (1.f + __expf(-x));
}

#define NBUF 4

__global__ __launch_bounds__(64) void recur_kernel(
    const float* __restrict__ proj,   // [MM][LDP] q|k|v|b|g|p1|p2|p3
    const int*   __restrict__ term,
    const float* __restrict__ tkp,
    const float* __restrict__ tvp,
    const float* __restrict__ sprev,
    const float* __restrict__ tick,
    __half* __restrict__ attn)        // [MM][512] half
{
    const int bh = blockIdx.x;
    const int b = bh >> 3;
    const int h = bh & 7;
    const int d = threadIdx.x;

    __shared__ __align__(16) float sstage[NBUF][5][64];
    __shared__ __align__(16) float sp[NBUF][3][4];
    __shared__ int sterm[NBUF];
    __shared__ float red[2][5][2];

    float ks[4][4], ss[4], vs[4];
#pragma unroll
    for (int e = 0; e < 4; e++) {
#pragma unroll
        for (int r = 0; r < 4; r++)
            ks[e][r] = tkp[((size_t)(b * RR + r) * HH + h) * FEAT + e * 64 + d];
        ss[e] = sprev[((size_t)(b * HH + h)) * FEAT + e * 64 + d];
    }
#pragma unroll
    for (int r = 0; r < 4; r++)
        vs[r] = tvp[((size_t)(b * RR + r) * HH + h) * HDd + d];

    const float PI = 3.14159265358979323846f;
    const float tk = tick[b];

    float cr0, cr1, cr2, cr3, sr0, sr1, sr2, sr3;
    float cw0, cw1, cw2, cw3, sw0, sw1, sw2, sw3;
    {
        float om0 = -PI;
        float om1 = -PI + 2.f * PI / 3.f;
        float om2 = -PI + 4.f * PI / 3.f;
        float om3 = PI;
        float a;
        a = (1.f + tk) * om0; cr0 = cosf(a); sr0 = sinf(a);
        a = (1.f + tk) * om1; cr1 = cosf(a); sr1 = sinf(a);
        a = (1.f + tk) * om2; cr2 = cosf(a); sr2 = sinf(a);
        a = (1.f + tk) * om3; cr3 = cosf(a); sr3 = sinf(a);
        cw0 = cosf(om0); sw0 = sinf(om0);
        cw1 = cosf(om1); sw1 = sinf(om1);
        cw2 = cosf(om2); sw2 = sinf(om2);
        cw3 = cosf(om3); sw3 = sinf(om3);
    }

    auto stage = [&](int t, int buf) {
        const int m = t * BB + b;
        {
            const int seg = d >> 4;
            const int j = (d & 15) * 4;
            const float* src = proj + (size_t)m * LDP + seg * 512 + h * HDd + j;
            unsigned dst = (unsigned)__cvta_generic_to_shared(&sstage[buf][seg][j]);
            asm volatile("cp.async.ca.shared.global [%0], [%1], 16;\n" :: "r"(dst), "l"(src));
        }
        if (d < 16) {
            const float* src = proj + (size_t)m * LDP + 4 * 512 + h * HDd + d * 4;
            unsigned dst = (unsigned)__cvta_generic_to_shared(&sstage[buf][4][d * 4]);
            asm volatile("cp.async.ca.shared.global [%0], [%1], 16;\n" :: "r"(dst), "l"(src));
        } else if (d < 19) {
            const int j = d - 16;
            const float* src = proj + (size_t)m * LDP + WROWS + j * 32 + h * ETA;
            unsigned dst = (unsigned)__cvta_generic_to_shared(&sp[buf][j][0]);
            asm volatile("cp.async.ca.shared.global [%0], [%1], 16;\n" :: "r"(dst), "l"(src));
        } else if (d == 19) {
            const int* src = term + m;
            unsigned dst = (unsigned)__cvta_generic_to_shared(&sterm[buf]);
            asm volatile("cp.async.ca.shared.global [%0], [%1], 4;\n" :: "r"(dst), "l"(src));
        }
        asm volatile("cp.async.commit_group;\n");
    };

    stage(0, 0);
    stage(1, 1);
    stage(2, 2);
    asm volatile("cp.async.wait_group 2;\n");
    __syncthreads();

    const int warp = d >> 5;

    for (int t = 0; t < TT; t++) {
        const int buf = t & (NBUF - 1);

        const float qd   = sstage[buf][0][d];
        const float kd   = sstage[buf][1][d];
        const float vv   = sstage[buf][2][d];
        const float bd   = sigf(sstage[buf][3][d]);
        const float gd   = sigf(sstage[buf][4][d]);
        const float tf   = 1.f - (float)sterm[buf];

        float v0 = 0.f, v1 = 0.f, v2 = 0.f, v3 = 0.f, v4 = 0.f;
#pragma unroll
        for (int e = 0; e < 4; e++) {
            const float phi = fmaxf(qd * sp[buf][1][e], 0.f);
            const float psi = fmaxf(kd * sp[buf][0][e], 0.f);
            const float gf  = gd * sigf(sp[buf][2][e]);
            const float gk  = psi * gf;
            const float dg  = (1.f - gf) * tf;

            ss[e] = dg * ss[e] + gk;
            v4 += ss[e] * phi;

            ks[e][0] = dg * ks[e][0] + gk * cr0;  v0 += ks[e][0] * phi;
            ks[e][1] = dg * ks[e][1] + gk * cr1;  v1 += ks[e][1] * phi;
            ks[e][2] = dg * ks[e][2] + gk * cr2;  v2 += ks[e][2] * phi;
            ks[e][3] = dg * ks[e][3] + gk * cr3;  v3 += ks[e][3] * phi;
        }

        const float bv = vv * bd;
        const float om = (1.f - bd) * tf;
        vs[0] = om * vs[0] + bv * cr0;
        vs[1] = om * vs[1] + bv * cr1;
        vs[2] = om * vs[2] + bv * cr2;
        vs[3] = om * vs[3] + bv * cr3;

#pragma unroll
        for (int o = 16; o > 0; o >>= 1) {
            v0 += __shfl_xor_sync(0xffffffffu, v0, o);
            v1 += __shfl_xor_sync(0xffffffffu, v1, o);
            v2 += __shfl_xor_sync(0xffffffffu, v2, o);
            v3 += __shfl_xor_sync(0xffffffffu, v3, o);
            v4 += __shfl_xor_sync(0xffffffffu, v4, o);
        }
        const int pb = t & 1;
        if ((d & 31) == 0) {
            red[pb][0][warp] = v0;
            red[pb][1][warp] = v1;
            red[pb][2][warp] = v2;
            red[pb][3][warp] = v3;
            red[pb][4][warp] = v4;
        }

        if (t + 3 < TT) {
            stage(t + 3, (t + 3) & (NBUF - 1));
            asm volatile("cp.async.wait_group 2;\n");
        } else if (t + 2 < TT) {
            asm volatile("cp.async.wait_group 1;\n");
        } else {
            asm volatile("cp.async.wait_group 0;\n");
        }
        __syncthreads();

        const float kdq0 = red[pb][0][0] + red[pb][0][1];
        const float kdq1 = red[pb][1][0] + red[pb][1][1];
        const float kdq2 = red[pb][2][0] + red[pb][2][1];
        const float kdq3 = red[pb][3][0] + red[pb][3][1];
        const float norm = red[pb][4][0] + red[pb][4][1];

        const float kv = vs[0] * kdq0 + vs[1] * kdq1 + vs[2] * kdq2 + vs[3] * kdq3;
        const int m = t * BB + b;
        attn[(size_t)m * DD + h * HDd + d] = __float2half_rn(kv / (8.f * norm + 1e-6f));

        float c2, s2;
        c2 = cr0 * cw0 - sr0 * sw0; s2 = sr0 * cw0 + cr0 * sw0; cr0 = c2; sr0 = s2;
        c2 = cr1 * cw1 - sr1 * sw1; s2 = sr1 * cw1 + cr1 * sw1; cr1 = c2; sr1 = s2;
        c2 = cr2 * cw2 - sr2 * sw2; s2 = sr2 * cw2 + cr2 * sw2; cr2 = c2; sr2 = s2;
        c2 = cr3 * cw3 - sr3 * sw3; s2 = sr3 * cw3 + cr3 * sw3; cr3 = c2; sr3 = s2;
    }
}

// ---------------------------------------------------------------------------
extern "C" void kernel_launch(void* const* d_in, const int* in_sizes, int n_in,
                              void* d_out, int out_size)
{
    const float* inputs = (const float*)d_in[0];
    const int*   term   = (const int*)d_in[1];
    const float* tkp    = (const float*)d_in[2];
    const float* tvp    = (const float*)d_in[3];
    const float* sprev  = (const float*)d_in[4];
    const float* tick   = (const float*)d_in[5];
    const float* Wq     = (const float*)d_in[6];
    const float* Wk     = (const float*)d_in[7];
    const float* Wv     = (const float*)d_in[8];
    const float* Wb     = (const float*)d_in[9];
    const float* Wg     = (const float*)d_in[10];
    const float* Wp1    = (const float*)d_in[11];
    const float* Wp2    = (const float*)d_in[12];
    const float* Wp3    = (const float*)d_in[13];
    const float* Wo     = (const float*)d_in[14];
    const float* bo     = (const float*)d_in[15];

    void* p;
    cudaGetSymbolAddress(&p, g_x);    __half* x    = (__half*)p;
    cudaGetSymbolAddress(&p, g_w5);   __half* w5   = (__half*)p;
    cudaGetSymbolAddress(&p, g_wo);   __half* wo   = (__half*)p;
    cudaGetSymbolAddress(&p, g_proj); float*  proj = (float*)p;
    cudaGetSymbolAddress(&p, g_attn); __half* attn = (__half*)p;

    const int WSZ = HH * HDd * DD;    // 262144
    const int PSZ = HH * ETA * DD;    // 16384

    cvt1_kernel<<<(MM * DD + 255) / 256, 256>>>(x, inputs, MM * DD);
    cvt5_kernel<<<(5 * WSZ + 255) / 256, 256>>>(w5, Wq, Wk, Wv, Wb, Wg, WSZ);
    cvtp_kernel<<<(4 * PSZ + 255) / 256, 256>>>(w5 + (size_t)WROWS * DD, Wp1, Wp2, Wp3, PSZ);
    cvt1_kernel<<<(WSZ + 255) / 256, 256>>>(wo, Wo, WSZ);

    // 1) Fused projection: (8192 x 2688) — q,k,v,beta,gamma,p1,p2,p3 (+pad)
    {
        dim3 grid(LDP / GBN, MM / GBM);   // (21, 64)
        mma_gemm<<<grid, 256>>>(x, w5, proj, MM, LDP, DD, LDP, nullptr);
    }
    // 2) Recurrence (64 threads per (b,h), one barrier per step)
    recur_kernel<<<BB * HH, 64>>>(proj, term, tkp, tvp, sprev, tick, attn);

    // 3) Output projection: out = attn @ Wo^T + bo  (8192 x 512)
    {
        dim3 grid(DD / GBN, MM / GBM);    // (4, 64)
        mma_gemm<<<grid, 256>>>(attn, wo, (float*)d_out, MM, DD, DD, DD, bo);
    }
}